// round 6
// baseline (speedup 1.0000x reference)
#include <cuda_runtime.h>

// ---------------------------------------------------------------------------
// out[i, :32] = sum_m sum_{j: t2m_j <= t1_i} (Q_i . Km_j) * Vm_j[:32]
//   Q = mlp3(m1, WQ); K_m = mlp3(m_m, WK[m]); V_m = m_m[:, :32]
// ---------------------------------------------------------------------------

#define T1        4096
#define TOTK      22528            // 4096+6144+8192+4096
#define CBLK      32               // key block size (state granularity)
#define NOBLK     704              // total key blocks (128+192+256+128)
#define NSTATE    708              // exclusive prefix states (nb+1 per modality)
#define NTILE     128              // query tiles of 32

typedef unsigned long long u64;

__device__ __forceinline__ u64 pk2(float lo, float hi) {
    u64 r; asm("mov.b64 %0,{%1,%2};" : "=l"(r) : "f"(lo), "f"(hi)); return r;
}
__device__ __forceinline__ void upk2(u64 v, float& lo, float& hi) {
    asm("mov.b64 {%0,%1},%2;" : "=f"(lo), "=f"(hi) : "l"(v));
}
__device__ __forceinline__ void ffma2(u64& d, u64 a, u64 b) {
    asm("fma.rn.f32x2 %0,%1,%2,%0;" : "+l"(d) : "l"(a), "l"(b));
}

// scratch (no allocations allowed)
__device__ float g_Q[T1 * 64];
__device__ float g_K[TOTK * 64];
__device__ float g_t2[TOTK];
__device__ float g_O[NOBLK * 2048];    // per-block sums  K^T V  (32-key blocks, 64 x 32)
__device__ float g_S[NSTATE * 2048];   // exclusive prefix states
__device__ float g_P[4][T1 * 32];      // per-modality partial outputs
__device__ int   g_cnt[NTILE][4][2];

__constant__ int c_T2[4]    = {4096, 6144, 8192, 4096};
__constant__ int c_KOFF[4]  = {0, 4096, 10240, 18432};
__constant__ int c_NB[4]    = {128, 192, 256, 128};
__constant__ int c_OOFF[5]  = {0, 128, 320, 576, 704};
__constant__ int c_SOFF[4]  = {0, 129, 322, 579};

// ---------------------------------------------------------------------------
// Kernel 1: fused 3-layer MLP. 32-row tiles (832 balanced blocks), 256 thr,
// 2x4 per-thread tiles. Hs holds DUPLICATED pairs so the f32x2 broadcast
// operand comes straight from LDS.128 (no mov.b64 packs in the hot loop).
// ---------------------------------------------------------------------------
__global__ void __launch_bounds__(256) mlp_kernel(
    const float* __restrict__ m1, const float* __restrict__ m2,
    const float* __restrict__ m3, const float* __restrict__ m4,
    const float* __restrict__ WQ_w, const float* __restrict__ WQ_b,
    const float* __restrict__ WK_w, const float* __restrict__ WK_b)
{
    __shared__ float Hs[64][72];   // [k][2*row] duplicated pairs (32 rows)
    __shared__ float Ws[64][68];   // [k][col]
    __shared__ float bs[64];

    const int task = blockIdx.y;
    const int rowsTab[5] = {4096, 4096, 6144, 8192, 4096};
    const int rows = rowsTab[task];
    const int row0 = blockIdx.x * 32;
    if (row0 >= rows) return;

    const float* X;
    if (task <= 1)      X = m1;
    else if (task == 2) X = m2;
    else if (task == 3) X = m3;
    else                X = m4;

    const float* Wb; const float* bb; float* out;
    if (task == 0) { Wb = WQ_w; bb = WQ_b; out = g_Q; }
    else {
        int m = task - 1;
        Wb = WK_w + m * 3 * 4096;
        bb = WK_b + m * 192;
        out = g_K + c_KOFF[m] * 64;
    }

    const int tid = threadIdx.x;
    // load X tile transposed + duplicated
    for (int idx = tid; idx < 2048; idx += 256) {
        int r = idx >> 6, c = idx & 63;
        float v = X[(row0 + r) * 64 + c];
        *(float2*)&Hs[c][2 * r] = make_float2(v, v);
    }

    const int rr0 = (tid & 15) * 2;    // row within tile (2 rows/thread)
    const int c0  = (tid >> 4) * 4;    // 4 cols/thread

    for (int l = 0; l < 3; l++) {
        for (int idx = tid; idx < 4096; idx += 256)
            Ws[idx >> 6][idx & 63] = Wb[l * 4096 + idx];
        if (tid < 64) bs[tid] = bb[l * 64 + tid];
        __syncthreads();

        u64 acc[2][2];
        #pragma unroll
        for (int rr = 0; rr < 2; rr++)
            #pragma unroll
            for (int cp = 0; cp < 2; cp++)
                acc[rr][cp] = pk2(bs[c0 + 2 * cp], bs[c0 + 2 * cp + 1]);

        #pragma unroll 16
        for (int k = 0; k < 64; k++) {
            ulonglong2 hd = *(const ulonglong2*)&Hs[k][2 * rr0]; // (h0,h0),(h1,h1)
            ulonglong2 w2 = *(const ulonglong2*)&Ws[k][c0];
            ffma2(acc[0][0], hd.x, w2.x); ffma2(acc[0][1], hd.x, w2.y);
            ffma2(acc[1][0], hd.y, w2.x); ffma2(acc[1][1], hd.y, w2.y);
        }

        float a[2][4];
        #pragma unroll
        for (int rr = 0; rr < 2; rr++)
            #pragma unroll
            for (int cp = 0; cp < 2; cp++)
                upk2(acc[rr][cp], a[rr][2 * cp], a[rr][2 * cp + 1]);

        if (l < 2) {
            #pragma unroll
            for (int rr = 0; rr < 2; rr++)
                #pragma unroll
                for (int cc = 0; cc < 4; cc++) a[rr][cc] = fmaxf(a[rr][cc], 0.0f);
        }
        __syncthreads();

        if (l < 2) {
            #pragma unroll
            for (int cc = 0; cc < 4; cc++) {
                // duplicated store: rows rr0, rr0+1 each twice
                *(float4*)&Hs[c0 + cc][2 * rr0] =
                    make_float4(a[0][cc], a[0][cc], a[1][cc], a[1][cc]);
            }
        } else {
            #pragma unroll
            for (int rr = 0; rr < 2; rr++)
                *(float4*)&out[(row0 + rr0 + rr) * 64 + c0] =
                    make_float4(a[rr][0], a[rr][1], a[rr][2], a[rr][3]);
        }
    }
}

// ---------------------------------------------------------------------------
// Kernel 2: per key-block outer-product sums O_b = K_blk^T V_blk (64 x 32)
// over 32-key blocks, and extraction of contiguous time arrays.
// ---------------------------------------------------------------------------
__global__ void __launch_bounds__(256) blocksum_kernel(
    const float* __restrict__ m1, const float* __restrict__ m2,
    const float* __restrict__ m3, const float* __restrict__ m4)
{
    __shared__ float Ks[32][68];
    __shared__ float Vs[32][32];

    const int blk = blockIdx.x;
    int m = 0;
    while (blk >= c_OOFF[m + 1]) m++;
    const int local = blk - c_OOFF[m];
    const float* X;
    if (m == 0) X = m1; else if (m == 1) X = m2; else if (m == 2) X = m3; else X = m4;

    const int j0g = c_KOFF[m] + local * CBLK;
    const int j0l = local * CBLK;
    const int tid = threadIdx.x;

    for (int idx = tid; idx < 2048; idx += 256) {
        int j = idx >> 6, d = idx & 63;
        Ks[j][d] = g_K[(j0g + j) * 64 + d];
    }
    for (int idx = tid; idx < 1024; idx += 256) {
        int j = idx >> 5, e = idx & 31;
        Vs[j][e] = X[(j0l + j) * 64 + e];
    }
    if (tid < 32) g_t2[j0g + tid] = X[(j0l + tid) * 64 + 63];
    __syncthreads();

    const int d1 = tid & 63;
    const int gg = tid >> 6;   // 0..3 -> e0 = gg*8
    u64 acc[4] = {0ULL, 0ULL, 0ULL, 0ULL};

    #pragma unroll 8
    for (int j = 0; j < CBLK; j++) {
        float kv = Ks[j][d1];
        u64 kd = pk2(kv, kv);
        ulonglong2 va = *(const ulonglong2*)&Vs[j][gg * 8];
        ulonglong2 vb = *(const ulonglong2*)&Vs[j][gg * 8 + 4];
        ffma2(acc[0], kd, va.x); ffma2(acc[1], kd, va.y);
        ffma2(acc[2], kd, vb.x); ffma2(acc[3], kd, vb.y);
    }
    float a[8];
    upk2(acc[0], a[0], a[1]); upk2(acc[1], a[2], a[3]);
    upk2(acc[2], a[4], a[5]); upk2(acc[3], a[6], a[7]);
    float* o = &g_O[blk * 2048 + d1 * 32 + gg * 8];
    *(float4*)o       = make_float4(a[0], a[1], a[2], a[3]);
    *(float4*)(o + 4) = make_float4(a[4], a[5], a[6], a[7]);
}

// ---------------------------------------------------------------------------
// Kernel 3: warp-parallel exclusive scan (one warp per (modality, elem);
// each lane covers nb/32 key-blocks, shfl-scan of lane sums) + the 1024
// tile binary searches fused in (blocks 1024..1027).
// ---------------------------------------------------------------------------
__global__ void __launch_bounds__(256) scan_search_kernel()
{
    const int blk = blockIdx.x;
    if (blk < 1024) {
        const int gw   = blk * 8 + (threadIdx.x >> 5);   // 0..8191
        const int lane = threadIdx.x & 31;
        const int m    = gw >> 11;
        const int el   = gw & 2047;
        const int nb   = c_NB[m];
        const int q    = nb >> 5;                        // 4,6,8,4
        const float* src = &g_O[c_OOFF[m] * 2048 + el];
        float* dst       = &g_S[c_SOFF[m] * 2048 + el];
        const int b0 = lane * q;

        float v[8];
        #pragma unroll
        for (int b = 0; b < 8; b++)
            v[b] = (b < q) ? src[(b0 + b) * 2048] : 0.0f;
        float s = 0.0f;
        #pragma unroll
        for (int b = 0; b < 8; b++) if (b < q) s += v[b];

        float incl = s;
        #pragma unroll
        for (int off = 1; off < 32; off <<= 1) {
            float t = __shfl_up_sync(0xffffffffu, incl, off);
            if (lane >= off) incl += t;
        }
        float run = incl - s;   // exclusive prefix of lane sums

        #pragma unroll
        for (int b = 0; b < 8; b++) {
            if (b < q) { dst[(b0 + b) * 2048] = run; run += v[b]; }
        }
        if (lane == 31) dst[nb * 2048] = run;
    } else {
        const int sid = (blk - 1024) * 256 + threadIdx.x;   // 0..1023
        const int tile = sid >> 3;
        const int m    = (sid >> 1) & 3;
        const int w    = sid & 1;
        const float target = g_t2[tile * 32 + (w ? 31 : 0)];
        const int ko = c_KOFF[m];
        int lo = 0, hi = c_T2[m];
        while (lo < hi) {
            int mid = (lo + hi) >> 1;
            if (g_t2[ko + mid] <= target) lo = mid + 1; else hi = mid;
        }
        g_cnt[tile][m][w] = lo;
    }
}

// ---------------------------------------------------------------------------
// Kernel 4: query kernel. One block = (32-query tile, modality). f32x2.
// State (Ss) and score (sc) buffers alias (disjoint lifetimes) to cut smem.
// ---------------------------------------------------------------------------
#define SC(j, i) SsSc[(j) * 33 + (i)]

__global__ void __launch_bounds__(256) query_kernel(
    const float* __restrict__ m1, const float* __restrict__ m2,
    const float* __restrict__ m3, const float* __restrict__ m4)
{
    __shared__ float Qs[64][33];     // [d][i]
    __shared__ float SsSc[64 * 33];  // state [d*32+e] then scores [j][i]
    __shared__ float Ks[64][68];     // key chunk [d][j]  (transposed)
    __shared__ float Vs[64][32];     // value chunk [j][e]
    __shared__ float t2s[64];

    const int tid = threadIdx.x;
    const int i   = tid & 31;
    const int g   = tid >> 5;
    const int e0  = g * 4;
    const int tile = blockIdx.x;
    const int m    = blockIdx.y;
    const int i0   = tile * 32;

    const float* X;
    if (m == 0) X = m1; else if (m == 1) X = m2; else if (m == 2) X = m3; else X = m4;
    const int ko = c_KOFF[m];

    const int cf = g_cnt[tile][m][0];
    const int cl = g_cnt[tile][m][1];
    const int B0 = cf >> 5;
    const int jstart = B0 << 5;
    const int jend = cl;

    for (int idx = tid; idx < 2048; idx += 256) {
        int r = idx >> 6, d = idx & 63;
        Qs[d][r] = g_Q[(i0 + r) * 64 + d];
    }
    const float* Sp = &g_S[(c_SOFF[m] + B0) * 2048];
    for (int idx = tid; idx < 2048; idx += 256) SsSc[idx] = Sp[idx];
    const float t1i = g_t2[i0 + i];
    __syncthreads();

    u64 a01 = 0ULL, a23 = 0ULL;   // output accumulators (e0..e0+3)

    // matvec: acc += Q_i . S_excl[B0][:, e0..e0+3]   (SsSc holds the state)
    #pragma unroll 8
    for (int d = 0; d < 64; d++) {
        float q = Qs[d][i];
        u64 qd = pk2(q, q);
        ulonglong2 s2 = *(const ulonglong2*)&SsSc[d * 32 + e0];
        ffma2(a01, qd, s2.x); ffma2(a23, qd, s2.y);
    }

    for (int jc = jstart; jc < jend; jc += 64) {
        const int nj = min(64, jend - jc);
        __syncthreads();   // prev chunk reads done; also retires state reads
        for (int idx = tid; idx < 4096; idx += 256) {
            int j = idx >> 6, d = idx & 63;
            Ks[d][j] = (j < nj) ? g_K[(ko + jc + j) * 64 + d] : 0.0f;
        }
        for (int idx = tid; idx < 2048; idx += 256) {
            int j = idx >> 5, e = idx & 31;
            Vs[j][e] = (j < nj) ? X[(jc + j) * 64 + e] : 0.0f;
        }
        if (tid < 64) t2s[tid] = (tid < nj) ? g_t2[ko + jc + tid] : 3.0e38f;
        __syncthreads();

        // scores: thread (i,g) computes j = g*8 .. g*8+7
        const int j0 = g * 8;
        u64 s01 = 0ULL, s23 = 0ULL, s45 = 0ULL, s67 = 0ULL;
        #pragma unroll 8
        for (int d = 0; d < 64; d++) {
            float q = Qs[d][i];
            u64 qd = pk2(q, q);
            ulonglong2 ka = *(const ulonglong2*)&Ks[d][j0];
            ulonglong2 kb = *(const ulonglong2*)&Ks[d][j0 + 4];
            ffma2(s01, qd, ka.x); ffma2(s23, qd, ka.y);
            ffma2(s45, qd, kb.x); ffma2(s67, qd, kb.y);
        }
        float sv[8];
        upk2(s01, sv[0], sv[1]); upk2(s23, sv[2], sv[3]);
        upk2(s45, sv[4], sv[5]); upk2(s67, sv[6], sv[7]);
        #pragma unroll
        for (int jj = 0; jj < 8; jj++)
            SC(j0 + jj, i) = (t2s[j0 + jj] <= t1i) ? sv[jj] : 0.0f;
        __syncthreads();

        // accumulate: acc[e0..] += sum_j sc[j][i] * V[j][e0..]
        #pragma unroll 8
        for (int j = 0; j < 64; j++) {
            float s = SC(j, i);
            u64 sd = pk2(s, s);
            ulonglong2 v2 = *(const ulonglong2*)&Vs[j][e0];
            ffma2(a01, sd, v2.x); ffma2(a23, sd, v2.y);
        }
    }

    float o0, o1, o2, o3;
    upk2(a01, o0, o1); upk2(a23, o2, o3);
    *(float4*)&g_P[m][(i0 + i) * 32 + e0] = make_float4(o0, o1, o2, o3);
}

// ---------------------------------------------------------------------------
// Kernel 5: sum the 4 per-modality partials into the output.
// ---------------------------------------------------------------------------
__global__ void __launch_bounds__(256) reduce_kernel(float* __restrict__ out)
{
    const int idx = (blockIdx.x * 256 + threadIdx.x);
    if (idx >= T1 * 32 / 4) return;
    float4 a = ((const float4*)g_P[0])[idx];
    float4 b = ((const float4*)g_P[1])[idx];
    float4 c = ((const float4*)g_P[2])[idx];
    float4 d = ((const float4*)g_P[3])[idx];
    float4 o;
    o.x = (a.x + b.x) + (c.x + d.x);
    o.y = (a.y + b.y) + (c.y + d.y);
    o.z = (a.z + b.z) + (c.z + d.z);
    o.w = (a.w + b.w) + (c.w + d.w);
    ((float4*)out)[idx] = o;
}

// ---------------------------------------------------------------------------
extern "C" void kernel_launch(void* const* d_in, const int* in_sizes, int n_in,
                              void* d_out, int out_size)
{
    const float* m1   = (const float*)d_in[0];
    const float* m2   = (const float*)d_in[1];
    const float* m3   = (const float*)d_in[2];
    const float* m4   = (const float*)d_in[3];
    const float* WQ_w = (const float*)d_in[4];
    const float* WQ_b = (const float*)d_in[5];
    const float* WK_w = (const float*)d_in[6];
    const float* WK_b = (const float*)d_in[7];
    float* out = (float*)d_out;

    mlp_kernel<<<dim3(256, 5), 256>>>(m1, m2, m3, m4, WQ_w, WQ_b, WK_w, WK_b);
    blocksum_kernel<<<NOBLK, 256>>>(m1, m2, m3, m4);
    scan_search_kernel<<<1028, 256>>>();
    query_kernel<<<dim3(NTILE, 4), 256>>>(m1, m2, m3, m4);
    reduce_kernel<<<(T1 * 32 / 4 + 255) / 256, 256>>>(out);
}

// round 7
// speedup vs baseline: 1.0714x; 1.0714x over previous
#include <cuda_runtime.h>

// ---------------------------------------------------------------------------
// out[i, :32] = sum_m sum_{j: t2m_j <= t1_i} (Q_i . Km_j) * Vm_j[:32]
//   Q = mlp3(m1, WQ); K_m = mlp3(m_m, WK[m]); V_m = m_m[:, :32]
// ---------------------------------------------------------------------------

#define T1        4096
#define TOTK      22528            // 4096+6144+8192+4096
#define CBLK      64               // key block size
#define NOBLK     352              // total key blocks (64+96+128+64)
#define NSTATE    356              // exclusive prefix states (nb+1 per modality)
#define NTILE     256              // query tiles of 16

typedef unsigned long long u64;

__device__ __forceinline__ u64 pk2(float lo, float hi) {
    u64 r; asm("mov.b64 %0,{%1,%2};" : "=l"(r) : "f"(lo), "f"(hi)); return r;
}
__device__ __forceinline__ void upk2(u64 v, float& lo, float& hi) {
    asm("mov.b64 {%0,%1},%2;" : "=f"(lo), "=f"(hi) : "l"(v));
}
__device__ __forceinline__ void ffma2(u64& d, u64 a, u64 b) {
    asm("fma.rn.f32x2 %0,%1,%2,%0;" : "+l"(d) : "l"(a), "l"(b));
}

// scratch (no allocations allowed)
__device__ float g_Q[T1 * 64];
__device__ float g_K[TOTK * 64];
__device__ float g_t2[TOTK];
__device__ float g_O[NOBLK * 2048];    // per-block sums  K^T V  (64 x 32)
__device__ float g_S[NSTATE * 2048];   // exclusive prefix states
__device__ float g_P[4][T1 * 32];      // per-modality partial outputs
__device__ int   g_cnt[NTILE][4][2];

__constant__ int c_T2[4]    = {4096, 6144, 8192, 4096};
__constant__ int c_KOFF[4]  = {0, 4096, 10240, 18432};
__constant__ int c_NB[4]    = {64, 96, 128, 64};
__constant__ int c_OOFF[5]  = {0, 64, 160, 288, 352};
__constant__ int c_SOFF[4]  = {0, 65, 162, 291};

// ---------------------------------------------------------------------------
// Kernel 1: fused 3-layer MLP. 256 threads, 64-row tile, 4x4 thread tiles,
// f32x2 packed FMA. (Round-5 proven config.)
// ---------------------------------------------------------------------------
__global__ void __launch_bounds__(256) mlp_kernel(
    const float* __restrict__ m1, const float* __restrict__ m2,
    const float* __restrict__ m3, const float* __restrict__ m4,
    const float* __restrict__ WQ_w, const float* __restrict__ WQ_b,
    const float* __restrict__ WK_w, const float* __restrict__ WK_b)
{
    __shared__ float Hs[64][68];   // [k][row]  (transposed activations)
    __shared__ float Ws[64][68];   // [k][col]
    __shared__ float bs[64];

    const int task = blockIdx.y;
    const int rowsTab[5] = {4096, 4096, 6144, 8192, 4096};
    const int rows = rowsTab[task];
    const int row0 = blockIdx.x * 64;
    if (row0 >= rows) return;

    const float* X;
    if (task <= 1)      X = m1;
    else if (task == 2) X = m2;
    else if (task == 3) X = m3;
    else                X = m4;

    const float* Wb; const float* bb; float* out;
    if (task == 0) { Wb = WQ_w; bb = WQ_b; out = g_Q; }
    else {
        int m = task - 1;
        Wb = WK_w + m * 3 * 4096;
        bb = WK_b + m * 192;
        out = g_K + c_KOFF[m] * 64;
    }

    const int tid = threadIdx.x;
    for (int idx = tid; idx < 4096; idx += 256) {
        int r = idx >> 6, c = idx & 63;
        Hs[c][r] = X[(row0 + r) * 64 + c];
    }

    const int r0 = (tid & 15) * 4;     // 16 row groups
    const int c0 = (tid >> 4) * 4;     // 16 col groups

    for (int l = 0; l < 3; l++) {
        for (int idx = tid; idx < 4096; idx += 256)
            Ws[idx >> 6][idx & 63] = Wb[l * 4096 + idx];
        if (tid < 64) bs[tid] = bb[l * 64 + tid];
        __syncthreads();

        u64 acc[4][2];   // [row][col-pair]
        #pragma unroll
        for (int rr = 0; rr < 4; rr++)
            #pragma unroll
            for (int cp = 0; cp < 2; cp++)
                acc[rr][cp] = pk2(bs[c0 + 2 * cp], bs[c0 + 2 * cp + 1]);

        #pragma unroll 8
        for (int k = 0; k < 64; k++) {
            float4 h = *(const float4*)&Hs[k][r0];
            ulonglong2 w2 = *(const ulonglong2*)&Ws[k][c0];
            u64 hd0 = pk2(h.x, h.x), hd1 = pk2(h.y, h.y);
            u64 hd2 = pk2(h.z, h.z), hd3 = pk2(h.w, h.w);
            ffma2(acc[0][0], hd0, w2.x); ffma2(acc[0][1], hd0, w2.y);
            ffma2(acc[1][0], hd1, w2.x); ffma2(acc[1][1], hd1, w2.y);
            ffma2(acc[2][0], hd2, w2.x); ffma2(acc[2][1], hd2, w2.y);
            ffma2(acc[3][0], hd3, w2.x); ffma2(acc[3][1], hd3, w2.y);
        }

        float a[4][4];
        #pragma unroll
        for (int rr = 0; rr < 4; rr++)
            #pragma unroll
            for (int cp = 0; cp < 2; cp++)
                upk2(acc[rr][cp], a[rr][2 * cp], a[rr][2 * cp + 1]);

        if (l < 2) {
            #pragma unroll
            for (int rr = 0; rr < 4; rr++)
                #pragma unroll
                for (int cc = 0; cc < 4; cc++) a[rr][cc] = fmaxf(a[rr][cc], 0.0f);
        }
        __syncthreads();

        if (l < 2) {
            #pragma unroll
            for (int cc = 0; cc < 4; cc++) {
                float4 v = make_float4(a[0][cc], a[1][cc], a[2][cc], a[3][cc]);
                *(float4*)&Hs[c0 + cc][r0] = v;
            }
        } else {
            #pragma unroll
            for (int rr = 0; rr < 4; rr++)
                *(float4*)&out[(row0 + r0 + rr) * 64 + c0] =
                    make_float4(a[rr][0], a[rr][1], a[rr][2], a[rr][3]);
        }
    }
}

// ---------------------------------------------------------------------------
// Kernel 2: per key-block outer-product sums O_b = K_blk^T V_blk (64 x 32),
// and extraction of contiguous time arrays. f32x2 packed.
// ---------------------------------------------------------------------------
__global__ void __launch_bounds__(256) blocksum_kernel(
    const float* __restrict__ m1, const float* __restrict__ m2,
    const float* __restrict__ m3, const float* __restrict__ m4)
{
    __shared__ float Ks[64][68];
    __shared__ float Vs[64][32];

    const int blk = blockIdx.x;
    int m = 0;
    while (blk >= c_OOFF[m + 1]) m++;
    const int local = blk - c_OOFF[m];
    const float* X;
    if (m == 0) X = m1; else if (m == 1) X = m2; else if (m == 2) X = m3; else X = m4;

    const int j0g = c_KOFF[m] + local * CBLK;
    const int j0l = local * CBLK;
    const int tid = threadIdx.x;

    for (int idx = tid; idx < 4096; idx += 256) {
        int j = idx >> 6, d = idx & 63;
        Ks[j][d] = g_K[(j0g + j) * 64 + d];
    }
    for (int idx = tid; idx < 2048; idx += 256) {
        int j = idx >> 5, e = idx & 31;
        Vs[j][e] = X[(j0l + j) * 64 + e];
    }
    if (tid < 64) g_t2[j0g + tid] = X[(j0l + tid) * 64 + 63];
    __syncthreads();

    const int d1 = tid & 63;
    const int gg = tid >> 6;   // 0..3 -> e0 = gg*8
    u64 acc[4] = {0ULL, 0ULL, 0ULL, 0ULL};

    #pragma unroll 8
    for (int j = 0; j < CBLK; j++) {
        float kv = Ks[j][d1];
        u64 kd = pk2(kv, kv);
        ulonglong2 va = *(const ulonglong2*)&Vs[j][gg * 8];
        ulonglong2 vb = *(const ulonglong2*)&Vs[j][gg * 8 + 4];
        ffma2(acc[0], kd, va.x); ffma2(acc[1], kd, va.y);
        ffma2(acc[2], kd, vb.x); ffma2(acc[3], kd, vb.y);
    }
    float a[8];
    upk2(acc[0], a[0], a[1]); upk2(acc[1], a[2], a[3]);
    upk2(acc[2], a[4], a[5]); upk2(acc[3], a[6], a[7]);
    float* o = &g_O[blk * 2048 + d1 * 32 + gg * 8];
    *(float4*)o       = make_float4(a[0], a[1], a[2], a[3]);
    *(float4*)(o + 4) = make_float4(a[4], a[5], a[6], a[7]);
}

// ---------------------------------------------------------------------------
// Kernel 3: warp-parallel exclusive scan (blocks 0..1023) + the 2048 tile
// binary searches (blocks 1024..1031).
// ---------------------------------------------------------------------------
__global__ void __launch_bounds__(256) scan_search_kernel()
{
    const int blk = blockIdx.x;
    if (blk < 1024) {
        const int gw   = blk * 8 + (threadIdx.x >> 5);   // 0..8191
        const int lane = threadIdx.x & 31;
        const int m    = gw >> 11;
        const int el   = gw & 2047;
        const int nb   = c_NB[m];
        const int q    = nb >> 5;                        // 2,3,4,2
        const float* src = &g_O[c_OOFF[m] * 2048 + el];
        float* dst       = &g_S[c_SOFF[m] * 2048 + el];
        const int b0 = lane * q;

        float v[4];
        #pragma unroll
        for (int b = 0; b < 4; b++)
            v[b] = (b < q) ? src[(b0 + b) * 2048] : 0.0f;
        float s = 0.0f;
        #pragma unroll
        for (int b = 0; b < 4; b++) if (b < q) s += v[b];

        float incl = s;
        #pragma unroll
        for (int off = 1; off < 32; off <<= 1) {
            float t = __shfl_up_sync(0xffffffffu, incl, off);
            if (lane >= off) incl += t;
        }
        float run = incl - s;   // exclusive prefix of lane sums

        #pragma unroll
        for (int b = 0; b < 4; b++) {
            if (b < q) { dst[(b0 + b) * 2048] = run; run += v[b]; }
        }
        if (lane == 31) dst[nb * 2048] = run;
    } else {
        const int sid = (blk - 1024) * 256 + threadIdx.x;   // 0..2047
        const int tile = sid >> 3;
        const int m    = (sid >> 1) & 3;
        const int w    = sid & 1;
        const float target = g_t2[tile * 16 + (w ? 15 : 0)];
        const int ko = c_KOFF[m];
        int lo = 0, hi = c_T2[m];
        while (lo < hi) {
            int mid = (lo + hi) >> 1;
            if (g_t2[ko + mid] <= target) lo = mid + 1; else hi = mid;
        }
        g_cnt[tile][m][w] = lo;
    }
}

// ---------------------------------------------------------------------------
// Kernel 4: query kernel. One block = (16-query tile, modality), 256 thr,
// 16 groups: e-width 2, 4 scores/thread. Grid = 1024 blocks (occ was the
// limiter at 512). State and score buffers alias (disjoint lifetimes).
// ---------------------------------------------------------------------------
#define SC(j, i) SsSc[(j) * 17 + (i)]

__global__ void __launch_bounds__(256) query_kernel(
    const float* __restrict__ m1, const float* __restrict__ m2,
    const float* __restrict__ m3, const float* __restrict__ m4)
{
    __shared__ float Qs[64][17];     // [d][i]  (16 queries)
    __shared__ float SsSc[2048];     // state [d*32+e] then scores [j*17+i]
    __shared__ float Ks[64][68];     // key chunk [d][j]  (transposed)
    __shared__ float Vs[64][32];     // value chunk [j][e]
    __shared__ float t2s[64];

    const int tid = threadIdx.x;
    const int i   = tid & 15;        // query within tile
    const int g   = tid >> 4;        // 0..15
    const int e0  = g * 2;           // output col pair
    const int tile = blockIdx.x;
    const int m    = blockIdx.y;
    const int i0   = tile * 16;

    const float* X;
    if (m == 0) X = m1; else if (m == 1) X = m2; else if (m == 2) X = m3; else X = m4;
    const int ko = c_KOFF[m];

    const int cf = g_cnt[tile][m][0];
    const int cl = g_cnt[tile][m][1];
    const int B0 = cf >> 6;
    const int jstart = B0 << 6;
    const int jend = cl;

    for (int idx = tid; idx < 1024; idx += 256) {
        int r = idx >> 6, d = idx & 63;
        Qs[d][r] = g_Q[(i0 + r) * 64 + d];
    }
    const float* Sp = &g_S[(c_SOFF[m] + B0) * 2048];
    for (int idx = tid; idx < 2048; idx += 256) SsSc[idx] = Sp[idx];
    const float t1i = g_t2[i0 + i];
    __syncthreads();

    u64 a01 = 0ULL;   // output accumulator (e0, e0+1)

    // matvec: acc += Q_i . S_excl[B0][:, e0..e0+1]
    #pragma unroll 8
    for (int d = 0; d < 64; d++) {
        float q = Qs[d][i];
        u64 qd = pk2(q, q);
        u64 s2 = *(const u64*)&SsSc[d * 32 + e0];
        ffma2(a01, qd, s2);
    }

    for (int jc = jstart; jc < jend; jc += 64) {
        const int nj = min(64, jend - jc);
        __syncthreads();   // prev chunk reads done; also retires state reads
        for (int idx = tid; idx < 4096; idx += 256) {
            int j = idx >> 6, d = idx & 63;
            Ks[d][j] = (j < nj) ? g_K[(ko + jc + j) * 64 + d] : 0.0f;
        }
        for (int idx = tid; idx < 2048; idx += 256) {
            int j = idx >> 5, e = idx & 31;
            Vs[j][e] = (j < nj) ? X[(jc + j) * 64 + e] : 0.0f;
        }
        if (tid < 64) t2s[tid] = (tid < nj) ? g_t2[ko + jc + tid] : 3.0e38f;
        __syncthreads();

        // scores: thread (i,g) computes j = g*4 .. g*4+3
        const int j0 = g * 4;
        u64 s01 = 0ULL, s23 = 0ULL;
        #pragma unroll 8
        for (int d = 0; d < 64; d++) {
            float q = Qs[d][i];
            u64 qd = pk2(q, q);
            ulonglong2 ka = *(const ulonglong2*)&Ks[d][j0];
            ffma2(s01, qd, ka.x); ffma2(s23, qd, ka.y);
        }
        float sv[4];
        upk2(s01, sv[0], sv[1]); upk2(s23, sv[2], sv[3]);
        #pragma unroll
        for (int jj = 0; jj < 4; jj++)
            SC(j0 + jj, i) = (t2s[j0 + jj] <= t1i) ? sv[jj] : 0.0f;
        __syncthreads();

        // accumulate: acc[e0..] += sum_j sc[j][i] * V[j][e0..e0+1]
        #pragma unroll 16
        for (int j = 0; j < 64; j++) {
            float s = SC(j, i);
            u64 sd = pk2(s, s);
            u64 v2 = *(const u64*)&Vs[j][e0];
            ffma2(a01, sd, v2);
        }
    }

    float o0, o1;
    upk2(a01, o0, o1);
    *(float2*)&g_P[m][(i0 + i) * 32 + e0] = make_float2(o0, o1);
}

// ---------------------------------------------------------------------------
// Kernel 5: sum the 4 per-modality partials into the output.
// ---------------------------------------------------------------------------
__global__ void __launch_bounds__(256) reduce_kernel(float* __restrict__ out)
{
    const int idx = (blockIdx.x * 256 + threadIdx.x);
    if (idx >= T1 * 32 / 4) return;
    float4 a = ((const float4*)g_P[0])[idx];
    float4 b = ((const float4*)g_P[1])[idx];
    float4 c = ((const float4*)g_P[2])[idx];
    float4 d = ((const float4*)g_P[3])[idx];
    float4 o;
    o.x = (a.x + b.x) + (c.x + d.x);
    o.y = (a.y + b.y) + (c.y + d.y);
    o.z = (a.z + b.z) + (c.z + d.z);
    o.w = (a.w + b.w) + (c.w + d.w);
    ((float4*)out)[idx] = o;
}

// ---------------------------------------------------------------------------
extern "C" void kernel_launch(void* const* d_in, const int* in_sizes, int n_in,
                              void* d_out, int out_size)
{
    const float* m1   = (const float*)d_in[0];
    const float* m2   = (const float*)d_in[1];
    const float* m3   = (const float*)d_in[2];
    const float* m4   = (const float*)d_in[3];
    const float* WQ_w = (const float*)d_in[4];
    const float* WQ_b = (const float*)d_in[5];
    const float* WK_w = (const float*)d_in[6];
    const float* WK_b = (const float*)d_in[7];
    float* out = (float*)d_out;

    mlp_kernel<<<dim3(128, 5), 256>>>(m1, m2, m3, m4, WQ_w, WQ_b, WK_w, WK_b);
    blocksum_kernel<<<NOBLK, 256>>>(m1, m2, m3, m4);
    scan_search_kernel<<<1032, 256>>>();
    query_kernel<<<dim3(NTILE, 4), 256>>>(m1, m2, m3, m4);
    reduce_kernel<<<(T1 * 32 / 4 + 255) / 256, 256>>>(out);
}

// round 8
// speedup vs baseline: 1.1831x; 1.1042x over previous
#include <cuda_runtime.h>

// ---------------------------------------------------------------------------
// out[i, :32] = sum_m sum_{j: t2m_j <= t1_i} (Q_i . Km_j) * Vm_j[:32]
//   Q = mlp3(m1, WQ); K_m = mlp3(m_m, WK[m]); V_m = m_m[:, :32]
// ---------------------------------------------------------------------------

#define T1        4096
#define TOTK      22528            // 4096+6144+8192+4096
#define CBLK      64               // key block size
#define NOBLK     352              // total key blocks (64+96+128+64)
#define NSTATE    356              // exclusive prefix states (nb+1 per modality)
#define NTILE     128              // query tiles of 32

typedef unsigned long long u64;

__device__ __forceinline__ u64 pk2(float lo, float hi) {
    u64 r; asm("mov.b64 %0,{%1,%2};" : "=l"(r) : "f"(lo), "f"(hi)); return r;
}
__device__ __forceinline__ void upk2(u64 v, float& lo, float& hi) {
    asm("mov.b64 {%0,%1},%2;" : "=f"(lo), "=f"(hi) : "l"(v));
}
__device__ __forceinline__ void ffma2(u64& d, u64 a, u64 b) {
    asm("fma.rn.f32x2 %0,%1,%2,%0;" : "+l"(d) : "l"(a), "l"(b));
}

// scratch (no allocations allowed)
__device__ float g_Q[T1 * 64];
__device__ float g_K[TOTK * 64];
__device__ float g_t2[TOTK];
__device__ float g_O[NOBLK * 2048];    // per-block sums  K^T V  (64 x 32)
__device__ float g_S[NSTATE * 2048];   // exclusive prefix states
__device__ float g_P[4][T1 * 32];      // per-modality partial outputs
__device__ int   g_cnt[NTILE][4][2];

__constant__ int c_T2[4]    = {4096, 6144, 8192, 4096};
__constant__ int c_KOFF[4]  = {0, 4096, 10240, 18432};
__constant__ int c_NB[4]    = {64, 96, 128, 64};
__constant__ int c_OOFF[5]  = {0, 64, 160, 288, 352};
__constant__ int c_SOFF[4]  = {0, 65, 162, 291};

// ---------------------------------------------------------------------------
// Kernel 1: fused 3-layer MLP + (for K tasks) per-block outer-product sums
// O_b = K_blk^T V_blk and t2 extraction. One block = one 64-row tile; for
// tasks 1..4 the tile IS one key block, so blocksum fuses for free.
// ---------------------------------------------------------------------------
__global__ void __launch_bounds__(256) mlp_kernel(
    const float* __restrict__ m1, const float* __restrict__ m2,
    const float* __restrict__ m3, const float* __restrict__ m4,
    const float* __restrict__ WQ_w, const float* __restrict__ WQ_b,
    const float* __restrict__ WK_w, const float* __restrict__ WK_b)
{
    __shared__ float Hs[64][68];   // [k][row] transposed activations; later V
    __shared__ float Ws[64][68];   // [k][col] weights; later K tile [j][d]
    __shared__ float bs[64];

    const int task = blockIdx.y;
    const int rowsTab[5] = {4096, 4096, 6144, 8192, 4096};
    const int rows = rowsTab[task];
    const int row0 = blockIdx.x * 64;
    if (row0 >= rows) return;

    const float* X;
    if (task <= 1)      X = m1;
    else if (task == 2) X = m2;
    else if (task == 3) X = m3;
    else                X = m4;

    const float* Wb; const float* bb; float* out;
    if (task == 0) { Wb = WQ_w; bb = WQ_b; out = g_Q; }
    else {
        int m = task - 1;
        Wb = WK_w + m * 3 * 4096;
        bb = WK_b + m * 192;
        out = g_K + c_KOFF[m] * 64;
    }

    const int tid = threadIdx.x;
    for (int idx = tid; idx < 4096; idx += 256) {
        int r = idx >> 6, c = idx & 63;
        Hs[c][r] = X[(row0 + r) * 64 + c];
    }

    const int r0 = (tid & 15) * 4;     // 16 row groups
    const int c0 = (tid >> 4) * 4;     // 16 col groups

    for (int l = 0; l < 3; l++) {
        for (int idx = tid; idx < 4096; idx += 256)
            Ws[idx >> 6][idx & 63] = Wb[l * 4096 + idx];
        if (tid < 64) bs[tid] = bb[l * 64 + tid];
        __syncthreads();

        u64 acc[4][2];   // [row][col-pair]
        #pragma unroll
        for (int rr = 0; rr < 4; rr++)
            #pragma unroll
            for (int cp = 0; cp < 2; cp++)
                acc[rr][cp] = pk2(bs[c0 + 2 * cp], bs[c0 + 2 * cp + 1]);

        #pragma unroll 8
        for (int k = 0; k < 64; k++) {
            float4 h = *(const float4*)&Hs[k][r0];
            ulonglong2 w2 = *(const ulonglong2*)&Ws[k][c0];
            u64 hd0 = pk2(h.x, h.x), hd1 = pk2(h.y, h.y);
            u64 hd2 = pk2(h.z, h.z), hd3 = pk2(h.w, h.w);
            ffma2(acc[0][0], hd0, w2.x); ffma2(acc[0][1], hd0, w2.y);
            ffma2(acc[1][0], hd1, w2.x); ffma2(acc[1][1], hd1, w2.y);
            ffma2(acc[2][0], hd2, w2.x); ffma2(acc[2][1], hd2, w2.y);
            ffma2(acc[3][0], hd3, w2.x); ffma2(acc[3][1], hd3, w2.y);
        }

        float a[4][4];
        #pragma unroll
        for (int rr = 0; rr < 4; rr++)
            #pragma unroll
            for (int cp = 0; cp < 2; cp++)
                upk2(acc[rr][cp], a[rr][2 * cp], a[rr][2 * cp + 1]);

        if (l < 2) {
            #pragma unroll
            for (int rr = 0; rr < 4; rr++)
                #pragma unroll
                for (int cc = 0; cc < 4; cc++) a[rr][cc] = fmaxf(a[rr][cc], 0.0f);
        }
        __syncthreads();

        if (l < 2) {
            #pragma unroll
            for (int cc = 0; cc < 4; cc++) {
                float4 v = make_float4(a[0][cc], a[1][cc], a[2][cc], a[3][cc]);
                *(float4*)&Hs[c0 + cc][r0] = v;
            }
        } else {
            // final layer: write K/Q to global; for K tasks also stage the
            // tile into Ws as Ks[j][d] for the fused blocksum.
            #pragma unroll
            for (int rr = 0; rr < 4; rr++) {
                float4 v = make_float4(a[rr][0], a[rr][1], a[rr][2], a[rr][3]);
                *(float4*)&out[(row0 + r0 + rr) * 64 + c0] = v;
                if (task > 0) *(float4*)&Ws[r0 + rr][c0] = v;
            }
        }
    }

    if (task == 0) return;

    // ---------------- fused blocksum: O_b = K^T V, t2 extraction ----------
    const int m = task - 1;
    // V tile into Hs area: Vs[j][e] = X[row0+j][e], e<32
    for (int idx = tid; idx < 2048; idx += 256) {
        int j = idx >> 5, e = idx & 31;
        Hs[j][e] = X[(row0 + j) * 64 + e];
    }
    if (tid < 64) g_t2[c_KOFF[m] + row0 + tid] = X[(row0 + tid) * 64 + 63];
    __syncthreads();

    const int d1 = tid & 63;
    const int gg = tid >> 6;   // 0..3 -> e0 = gg*8
    u64 acc2[4] = {0ULL, 0ULL, 0ULL, 0ULL};

    #pragma unroll 8
    for (int j = 0; j < CBLK; j++) {
        float kv = Ws[j][d1];
        u64 kd = pk2(kv, kv);
        ulonglong2 va = *(const ulonglong2*)&Hs[j][gg * 8];
        ulonglong2 vb = *(const ulonglong2*)&Hs[j][gg * 8 + 4];
        ffma2(acc2[0], kd, va.x); ffma2(acc2[1], kd, va.y);
        ffma2(acc2[2], kd, vb.x); ffma2(acc2[3], kd, vb.y);
    }
    float a2[8];
    upk2(acc2[0], a2[0], a2[1]); upk2(acc2[1], a2[2], a2[3]);
    upk2(acc2[2], a2[4], a2[5]); upk2(acc2[3], a2[6], a2[7]);
    const int blk = c_OOFF[m] + (row0 >> 6);
    float* o = &g_O[blk * 2048 + d1 * 32 + gg * 8];
    *(float4*)o       = make_float4(a2[0], a2[1], a2[2], a2[3]);
    *(float4*)(o + 4) = make_float4(a2[4], a2[5], a2[6], a2[7]);
}

// ---------------------------------------------------------------------------
// Kernel 2: warp-parallel exclusive scan (blocks 0..1023) + the 1024 tile
// binary searches (blocks 1024..1027).
// ---------------------------------------------------------------------------
__global__ void __launch_bounds__(256) scan_search_kernel()
{
    const int blk = blockIdx.x;
    if (blk < 1024) {
        const int gw   = blk * 8 + (threadIdx.x >> 5);   // 0..8191
        const int lane = threadIdx.x & 31;
        const int m    = gw >> 11;
        const int el   = gw & 2047;
        const int nb   = c_NB[m];
        const int q    = nb >> 5;                        // 2,3,4,2
        const float* src = &g_O[c_OOFF[m] * 2048 + el];
        float* dst       = &g_S[c_SOFF[m] * 2048 + el];
        const int b0 = lane * q;

        float v[4];
        #pragma unroll
        for (int b = 0; b < 4; b++)
            v[b] = (b < q) ? src[(b0 + b) * 2048] : 0.0f;
        float s = 0.0f;
        #pragma unroll
        for (int b = 0; b < 4; b++) if (b < q) s += v[b];

        float incl = s;
        #pragma unroll
        for (int off = 1; off < 32; off <<= 1) {
            float t = __shfl_up_sync(0xffffffffu, incl, off);
            if (lane >= off) incl += t;
        }
        float run = incl - s;   // exclusive prefix of lane sums

        #pragma unroll
        for (int b = 0; b < 4; b++) {
            if (b < q) { dst[(b0 + b) * 2048] = run; run += v[b]; }
        }
        if (lane == 31) dst[nb * 2048] = run;
    } else {
        const int sid = (blk - 1024) * 256 + threadIdx.x;   // 0..1023
        const int tile = sid >> 3;
        const int m    = (sid >> 1) & 3;
        const int w    = sid & 1;
        const float target = g_t2[tile * 32 + (w ? 31 : 0)];
        const int ko = c_KOFF[m];
        int lo = 0, hi = c_T2[m];
        while (lo < hi) {
            int mid = (lo + hi) >> 1;
            if (g_t2[ko + mid] <= target) lo = mid + 1; else hi = mid;
        }
        g_cnt[tile][m][w] = lo;
    }
}

// ---------------------------------------------------------------------------
// Kernel 3: query kernel. One block = (32-query tile, modality). f32x2.
// 64-key chunks; Ks transposed; state/score buffers aliased.
// (Measured-best round-6 configuration, with CBLK=64.)
// ---------------------------------------------------------------------------
#define SC(j, i) SsSc[(j) * 33 + (i)]

__global__ void __launch_bounds__(256) query_kernel(
    const float* __restrict__ m1, const float* __restrict__ m2,
    const float* __restrict__ m3, const float* __restrict__ m4)
{
    __shared__ float Qs[64][33];     // [d][i]
    __shared__ float SsSc[64 * 33];  // state [d*32+e] then scores [j][i]
    __shared__ float Ks[64][68];     // key chunk [d][j]  (transposed)
    __shared__ float Vs[64][32];     // value chunk [j][e]
    __shared__ float t2s[64];

    const int tid = threadIdx.x;
    const int i   = tid & 31;
    const int g   = tid >> 5;
    const int e0  = g * 4;
    const int tile = blockIdx.x;
    const int m    = blockIdx.y;
    const int i0   = tile * 32;

    const float* X;
    if (m == 0) X = m1; else if (m == 1) X = m2; else if (m == 2) X = m3; else X = m4;
    const int ko = c_KOFF[m];

    const int cf = g_cnt[tile][m][0];
    const int cl = g_cnt[tile][m][1];
    const int B0 = cf >> 6;
    const int jstart = B0 << 6;
    const int jend = cl;

    for (int idx = tid; idx < 2048; idx += 256) {
        int r = idx >> 6, d = idx & 63;
        Qs[d][r] = g_Q[(i0 + r) * 64 + d];
    }
    const float* Sp = &g_S[(c_SOFF[m] + B0) * 2048];
    for (int idx = tid; idx < 2048; idx += 256) SsSc[idx] = Sp[idx];
    const float t1i = g_t2[i0 + i];
    __syncthreads();

    u64 a01 = 0ULL, a23 = 0ULL;   // output accumulators (e0..e0+3)

    // matvec: acc += Q_i . S_excl[B0][:, e0..e0+3]   (SsSc holds the state)
    #pragma unroll 8
    for (int d = 0; d < 64; d++) {
        float q = Qs[d][i];
        u64 qd = pk2(q, q);
        ulonglong2 s2 = *(const ulonglong2*)&SsSc[d * 32 + e0];
        ffma2(a01, qd, s2.x); ffma2(a23, qd, s2.y);
    }

    for (int jc = jstart; jc < jend; jc += 64) {
        const int nj = min(64, jend - jc);
        __syncthreads();   // prev chunk reads done; also retires state reads
        for (int idx = tid; idx < 4096; idx += 256) {
            int j = idx >> 6, d = idx & 63;
            Ks[d][j] = (j < nj) ? g_K[(ko + jc + j) * 64 + d] : 0.0f;
        }
        for (int idx = tid; idx < 2048; idx += 256) {
            int j = idx >> 5, e = idx & 31;
            Vs[j][e] = (j < nj) ? X[(jc + j) * 64 + e] : 0.0f;
        }
        if (tid < 64) t2s[tid] = (tid < nj) ? g_t2[ko + jc + tid] : 3.0e38f;
        __syncthreads();

        // scores: thread (i,g) computes j = g*8 .. g*8+7
        const int j0 = g * 8;
        u64 s01 = 0ULL, s23 = 0ULL, s45 = 0ULL, s67 = 0ULL;
        #pragma unroll 8
        for (int d = 0; d < 64; d++) {
            float q = Qs[d][i];
            u64 qd = pk2(q, q);
            ulonglong2 ka = *(const ulonglong2*)&Ks[d][j0];
            ulonglong2 kb = *(const ulonglong2*)&Ks[d][j0 + 4];
            ffma2(s01, qd, ka.x); ffma2(s23, qd, ka.y);
            ffma2(s45, qd, kb.x); ffma2(s67, qd, kb.y);
        }
        float sv[8];
        upk2(s01, sv[0], sv[1]); upk2(s23, sv[2], sv[3]);
        upk2(s45, sv[4], sv[5]); upk2(s67, sv[6], sv[7]);
        #pragma unroll
        for (int jj = 0; jj < 8; jj++)
            SC(j0 + jj, i) = (t2s[j0 + jj] <= t1i) ? sv[jj] : 0.0f;
        __syncthreads();

        // accumulate: acc[e0..] += sum_j sc[j][i] * V[j][e0..]
        #pragma unroll 8
        for (int j = 0; j < 64; j++) {
            float s = SC(j, i);
            u64 sd = pk2(s, s);
            ulonglong2 v2 = *(const ulonglong2*)&Vs[j][e0];
            ffma2(a01, sd, v2.x); ffma2(a23, sd, v2.y);
        }
    }

    float o0, o1, o2, o3;
    upk2(a01, o0, o1); upk2(a23, o2, o3);
    *(float4*)&g_P[m][(i0 + i) * 32 + e0] = make_float4(o0, o1, o2, o3);
}

// ---------------------------------------------------------------------------
// Kernel 4: sum the 4 per-modality partials into the output.
// ---------------------------------------------------------------------------
__global__ void __launch_bounds__(256) reduce_kernel(float* __restrict__ out)
{
    const int idx = (blockIdx.x * 256 + threadIdx.x);
    if (idx >= T1 * 32 / 4) return;
    float4 a = ((const float4*)g_P[0])[idx];
    float4 b = ((const float4*)g_P[1])[idx];
    float4 c = ((const float4*)g_P[2])[idx];
    float4 d = ((const float4*)g_P[3])[idx];
    float4 o;
    o.x = (a.x + b.x) + (c.x + d.x);
    o.y = (a.y + b.y) + (c.y + d.y);
    o.z = (a.z + b.z) + (c.z + d.z);
    o.w = (a.w + b.w) + (c.w + d.w);
    ((float4*)out)[idx] = o;
}

// ---------------------------------------------------------------------------
extern "C" void kernel_launch(void* const* d_in, const int* in_sizes, int n_in,
                              void* d_out, int out_size)
{
    const float* m1   = (const float*)d_in[0];
    const float* m2   = (const float*)d_in[1];
    const float* m3   = (const float*)d_in[2];
    const float* m4   = (const float*)d_in[3];
    const float* WQ_w = (const float*)d_in[4];
    const float* WQ_b = (const float*)d_in[5];
    const float* WK_w = (const float*)d_in[6];
    const float* WK_b = (const float*)d_in[7];
    float* out = (float*)d_out;

    mlp_kernel<<<dim3(128, 5), 256>>>(m1, m2, m3, m4, WQ_w, WQ_b, WK_w, WK_b);
    scan_search_kernel<<<1028, 256>>>();
    query_kernel<<<dim3(NTILE, 4), 256>>>(m1, m2, m3, m4);
    reduce_kernel<<<(T1 * 32 / 4 + 255) / 256, 256>>>(out);
}